// round 7
// baseline (speedup 1.0000x reference)
#include <cuda_runtime.h>
#include <cuda_bf16.h>
#include <math.h>
#include <stdint.h>

#define B 8
#define L 2048
#define D 64
#define BL (B*L)

// ---------------- device scratch ----------------
__device__ __nv_bfloat16 g_qn[BL * D];
__device__ __nv_bfloat16 g_kn[BL * D];
__device__ __nv_bfloat16 g_vb[BL * D];
__device__ float g_vsum[B * D];
__device__ float g_ksum[B * D];      // per-batch sum of normalized k rows
__device__ float g_M[B * D * D];     // per-batch M = sum_k khat khat^T
__device__ float g_logZ[BL];
__device__ float g_invZ[BL];

// ---------------- PTX helpers ----------------
static __device__ __forceinline__ uint32_t smem_u32(const void* p) {
    return (uint32_t)__cvta_generic_to_shared(p);
}
static __device__ __forceinline__ void ldmat_x4(uint32_t& r0, uint32_t& r1, uint32_t& r2, uint32_t& r3, uint32_t addr) {
    asm volatile("ldmatrix.sync.aligned.m8n8.x4.shared.b16 {%0,%1,%2,%3}, [%4];"
                 : "=r"(r0), "=r"(r1), "=r"(r2), "=r"(r3) : "r"(addr));
}
static __device__ __forceinline__ void ldmat_x4_t(uint32_t& r0, uint32_t& r1, uint32_t& r2, uint32_t& r3, uint32_t addr) {
    asm volatile("ldmatrix.sync.aligned.m8n8.x4.trans.shared.b16 {%0,%1,%2,%3}, [%4];"
                 : "=r"(r0), "=r"(r1), "=r"(r2), "=r"(r3) : "r"(addr));
}
static __device__ __forceinline__ void mma_bf16(float& c0, float& c1, float& c2, float& c3,
    uint32_t a0, uint32_t a1, uint32_t a2, uint32_t a3, uint32_t b0, uint32_t b1) {
    asm volatile("mma.sync.aligned.m16n8k16.row.col.f32.bf16.bf16.f32 "
                 "{%0,%1,%2,%3}, {%4,%5,%6,%7}, {%8,%9}, {%0,%1,%2,%3};"
                 : "+f"(c0), "+f"(c1), "+f"(c2), "+f"(c3)
                 : "r"(a0), "r"(a1), "r"(a2), "r"(a3), "r"(b0), "r"(b1));
}
static __device__ __forceinline__ uint32_t pack2(float lo, float hi) {
    __nv_bfloat162 h = __floats2bfloat162_rn(lo, hi);
    return *reinterpret_cast<uint32_t*>(&h);
}
// e^s - 1 for |s| <= 0.04: cubic Taylor, abs err <= 1.1e-7. FMA pipe only.
static __device__ __forceinline__ float expm1s(float s) {
    float u = fmaf(s, 0.166666667f, 0.5f);
    u = fmaf(s, u, 1.0f);
    return s * u;
}

// ---------------- K0: zero accumulators ----------------
__global__ void k_zero() {
    int i = blockIdx.x * 256 + threadIdx.x;          // 128 blocks -> covers 32768
    if (i < B * D * D) g_M[i] = 0.0f;
    if (i < B * D) { g_ksum[i] = 0.0f; g_vsum[i] = 0.0f; }
}

// ---------------- K1a: l2-normalize q,k -> bf16 (one warp per row) ----------------
__global__ void k_prep_qk(const float* __restrict__ q, const float* __restrict__ k) {
    const int w = threadIdx.x >> 5, lane = threadIdx.x & 31;
    const long row = (long)blockIdx.x * 8 + w;
    const float* src;
    __nv_bfloat16* dst;
    long r;
    if (row < BL) { src = q; dst = g_qn; r = row; }
    else          { src = k; dst = g_kn; r = row - BL; }
    float2 x = *(const float2*)&src[r * 64 + lane * 2];
    float ss = x.x * x.x + x.y * x.y;
#pragma unroll
    for (int o = 16; o; o >>= 1) ss += __shfl_xor_sync(0xFFFFFFFFu, ss, o);
    float inv = 1.0f / fmaxf(sqrtf(ss), 1e-12f);
    __nv_bfloat162 h = __floats2bfloat162_rn(x.x * inv, x.y * inv);
    *(__nv_bfloat162*)&dst[r * 64 + lane * 2] = h;
}

// ---------------- K1b: v -> bf16 and per-batch column sums ----------------
__global__ void k_prep_v(const float* __restrict__ v) {
    __shared__ float red[4][64];
    const int t = threadIdx.x;
    const int d = t & 63, g = t >> 6;
    const long base = (long)blockIdx.x * 64;
    const int b = (int)(base >> 11);
    float s = 0.0f;
#pragma unroll
    for (int i = 0; i < 16; i++) {
        long r = base + g + 4 * i;
        float x = v[r * 64 + d];
        s += x;
        g_vb[r * 64 + d] = __float2bfloat16_rn(x);
    }
    red[g][d] = s;
    __syncthreads();
    if (t < 64) {
        float tot = red[0][t] + red[1][t] + red[2][t] + red[3][t];
        atomicAdd(&g_vsum[b * 64 + t], tot);
    }
}

// ---------------- K1c: M = sum khat khat^T and ksum = sum khat (per batch) ----------------
// grid (16, B): each CTA reduces a 128-row chunk of one batch's khat.
__global__ void __launch_bounds__(256) k_moment() {
    __shared__ __align__(16) __nv_bfloat16 kc[128][64];   // 16 KB
    const int t = threadIdx.x;
    const int ct = blockIdx.x, b = blockIdx.y;
    const __nv_bfloat16* kg = g_kn + ((long)b * L + ct * 128) * 64;
    // 128 rows x 64 bf16 = 1024 uint4 (uint4 = 8 bf16)
#pragma unroll
    for (int i = 0; i < 4; i++) {
        int f = t + 256 * i;           // 0..1023
        int row = f >> 3, c = f & 7;
        *(uint4*)&kc[row][c * 8] = *(const uint4*)&kg[row * 64 + c * 8];
    }
    __syncthreads();

    if (t < 64) {
        float s = 0.0f;
#pragma unroll
        for (int r = 0; r < 128; r++) s += __bfloat162float(kc[r][t]);
        atomicAdd(&g_ksum[b * 64 + t], s);
    }

    const int i0 = t >> 2, j0 = (t & 3) * 16;
    float acc[16];
#pragma unroll
    for (int j = 0; j < 16; j++) acc[j] = 0.0f;
    for (int r = 0; r < 128; r++) {
        float a = __bfloat162float(kc[r][i0]);
        const __nv_bfloat162* p = (const __nv_bfloat162*)&kc[r][j0];
#pragma unroll
        for (int j2 = 0; j2 < 8; j2++) {
            float2 f2 = __bfloat1622float2(p[j2]);
            acc[2 * j2]     = fmaf(a, f2.x, acc[2 * j2]);
            acc[2 * j2 + 1] = fmaf(a, f2.y, acc[2 * j2 + 1]);
        }
    }
#pragma unroll
    for (int j = 0; j < 16; j++)
        atomicAdd(&g_M[(long)b * 4096 + i0 * 64 + j0 + j], acc[j]);
}

// ---------------- K1d: per-row Z via moments ----------------
// z = 2048 + qhat.ksum/25 + qhat^T M qhat / 1250
// grid (32, B): CTA = 64 q rows; thread t: row r = t>>2, j-quarter (t&3).
__global__ void __launch_bounds__(256) k_z() {
    __shared__ float Ms[64][64];                          // 16 KB
    __shared__ __align__(16) __nv_bfloat16 qs[64][64];    // 8 KB
    __shared__ float ksums[64];
    const int t = threadIdx.x;
    const int ct = blockIdx.x, b = blockIdx.y;

    const float* Mg = g_M + (long)b * 4096;
#pragma unroll
    for (int i = 0; i < 4; i++) {
        int f = t + 256 * i;           // 1024 float4
        *(float4*)&Ms[0][0 + f * 4] = *(const float4*)&Mg[f * 4];
    }
    const __nv_bfloat16* qg = g_qn + ((long)b * L + ct * 64) * 64;
    // 64 rows x 64 bf16 = 512 uint4 (uint4 = 8 bf16)
#pragma unroll
    for (int i = 0; i < 2; i++) {
        int f = t + 256 * i;           // 0..511
        int row = f >> 3, c = f & 7;
        *(uint4*)&qs[row][c * 8] = *(const uint4*)&qg[row * 64 + c * 8];
    }
    if (t < 64) ksums[t] = g_ksum[b * 64 + t];
    __syncthreads();

    const int r = t >> 2, j0 = (t & 3) * 16;
    float qj[16];
    {
        const __nv_bfloat162* p = (const __nv_bfloat162*)&qs[r][j0];
#pragma unroll
        for (int j2 = 0; j2 < 8; j2++) {
            float2 f2 = __bfloat1622float2(p[j2]);
            qj[2 * j2] = f2.x; qj[2 * j2 + 1] = f2.y;
        }
    }
    float uj[16];
#pragma unroll
    for (int j = 0; j < 16; j++) uj[j] = 0.0f;
    for (int i = 0; i < 64; i++) {
        float qi = __bfloat162float(qs[r][i]);
#pragma unroll
        for (int j4 = 0; j4 < 4; j4++) {
            float4 m = *(float4*)&Ms[i][j0 + j4 * 4];
            uj[j4 * 4 + 0] = fmaf(qi, m.x, uj[j4 * 4 + 0]);
            uj[j4 * 4 + 1] = fmaf(qi, m.y, uj[j4 * 4 + 1]);
            uj[j4 * 4 + 2] = fmaf(qi, m.z, uj[j4 * 4 + 2]);
            uj[j4 * 4 + 3] = fmaf(qi, m.w, uj[j4 * 4 + 3]);
        }
    }
    float quad = 0.0f, sk = 0.0f;
#pragma unroll
    for (int j = 0; j < 16; j++) {
        quad = fmaf(uj[j], qj[j], quad);
        sk   = fmaf(ksums[j0 + j], qj[j], sk);
    }
    quad += __shfl_xor_sync(0xFFFFFFFFu, quad, 1);
    quad += __shfl_xor_sync(0xFFFFFFFFu, quad, 2);
    sk   += __shfl_xor_sync(0xFFFFFFFFu, sk, 1);
    sk   += __shfl_xor_sync(0xFFFFFFFFu, sk, 2);
    if ((t & 3) == 0) {
        long row = (long)b * L + ct * 64 + r;
        float z = 2048.0f + sk * 0.04f + quad * 0.0008f;   // 0.0008 = 1/1250
        g_logZ[row] = logf(z);
        g_invZ[row] = 1.0f / z;
    }
}

// ---------------- K2: single-pass main kernel ----------------
// CTA = 128 q rows of one batch. QK mma -> s; write attn & log_attn (streaming);
// AV mma with t = e^s - 1; out = (vsum + t@v)/Z.
__global__ void __launch_bounds__(256) k_main(float* __restrict__ attn,
                                              float* __restrict__ lattn,
                                              float* __restrict__ out) {
    __shared__ __align__(16) __nv_bfloat16 sm0[128][72];  // q tile, later v chunk
    __shared__ __align__(16) __nv_bfloat16 sm1[128][72];  // k chunk
    const int t = threadIdx.x, w = t >> 5, lane = t & 31;
    const int qt = blockIdx.x, b = blockIdx.y;
    const int r = lane >> 2, c2 = (lane & 3) * 2;
    const float scale = 0.04f;   // 1/25

    const __nv_bfloat16* qg = g_qn + ((long)b * L + qt * 128) * 64;
    const __nv_bfloat16* kg = g_kn + (long)b * L * 64;
    const __nv_bfloat16* vg = g_vb + (long)b * L * 64;

    const long rowA = (long)b * L + qt * 128 + w * 16 + r;
    const float lzA = g_logZ[rowA], lzB = g_logZ[rowA + 8];
    const float izA = g_invZ[rowA], izB = g_invZ[rowA + 8];

    // ---- prologue: q tile -> smem -> A fragments ----
#pragma unroll
    for (int i = 0; i < 4; i++) {
        int f = t + 256 * i;
        int row = f >> 3, c = f & 7;
        *(uint4*)&sm0[row][c * 8] = *(const uint4*)&qg[row * 64 + c * 8];
    }
    __syncthreads();
    uint32_t A[4][4];
#pragma unroll
    for (int ksi = 0; ksi < 4; ksi++) {
        uint32_t addr = smem_u32(&sm0[w * 16 + (lane & 15)][ksi * 16 + ((lane >> 4) << 3)]);
        ldmat_x4(A[ksi][0], A[ksi][1], A[ksi][2], A[ksi][3], addr);
    }

    float* aA = attn + rowA * L;
    float* aB = aA + (long)8 * L;
    float* lA = lattn + rowA * L;
    float* lB = lA + (long)8 * L;

    float acc[8][4];
#pragma unroll
    for (int i = 0; i < 8; i++)
#pragma unroll
        for (int j = 0; j < 4; j++) acc[i][j] = 0.0f;

    {
        uint4 ktmp[4], vtmp[4];
#pragma unroll
        for (int i = 0; i < 4; i++) {
            int f = t + 256 * i;
            int row = f >> 3, c = f & 7;
            ktmp[i] = *(const uint4*)&kg[row * 64 + c * 8];
            vtmp[i] = *(const uint4*)&vg[row * 64 + c * 8];
        }
        for (int kc = 0; kc < 16; kc++) {
            __syncthreads();
#pragma unroll
            for (int i = 0; i < 4; i++) {
                int f = t + 256 * i;
                int row = f >> 3, c = f & 7;
                *(uint4*)&sm1[row][c * 8] = ktmp[i];
                *(uint4*)&sm0[row][c * 8] = vtmp[i];
            }
            __syncthreads();
            if (kc < 15) {
#pragma unroll
                for (int i = 0; i < 4; i++) {
                    int f = t + 256 * i;
                    int row = f >> 3, c = f & 7;
                    ktmp[i] = *(const uint4*)&kg[((kc + 1) * 128 + row) * 64 + c * 8];
                    vtmp[i] = *(const uint4*)&vg[((kc + 1) * 128 + row) * 64 + c * 8];
                }
            }
#pragma unroll
            for (int nt2 = 0; nt2 < 8; nt2++) {
                float cf[2][4] = {{0.f,0.f,0.f,0.f},{0.f,0.f,0.f,0.f}};
#pragma unroll
                for (int ksi = 0; ksi < 4; ksi++) {
                    uint32_t b0, b1, b2, b3;
                    uint32_t addr = smem_u32(&sm1[nt2 * 16 + ((lane >> 4) << 3) + (lane & 7)]
                                                  [ksi * 16 + (((lane >> 3) & 1) << 3)]);
                    ldmat_x4(b0, b1, b2, b3, addr);
                    mma_bf16(cf[0][0], cf[0][1], cf[0][2], cf[0][3], A[ksi][0], A[ksi][1], A[ksi][2], A[ksi][3], b0, b1);
                    mma_bf16(cf[1][0], cf[1][1], cf[1][2], cf[1][3], A[ksi][0], A[ksi][1], A[ksi][2], A[ksi][3], b2, b3);
                }
                const int col0 = kc * 128 + nt2 * 16 + c2;
                float s00 = cf[0][0] * scale, s01 = cf[0][1] * scale;  // row r,   cols c2
                float s10 = cf[0][2] * scale, s11 = cf[0][3] * scale;  // row r+8, cols c2
                float s20 = cf[1][0] * scale, s21 = cf[1][1] * scale;  // row r,   cols c2+8
                float s30 = cf[1][2] * scale, s31 = cf[1][3] * scale;  // row r+8, cols c2+8
                float t00 = expm1s(s00), t01 = expm1s(s01);
                float t10 = expm1s(s10), t11 = expm1s(s11);
                float t20 = expm1s(s20), t21 = expm1s(s21);
                float t30 = expm1s(s30), t31 = expm1s(s31);
                __stcs((float2*)&lA[col0],     make_float2(s00 - lzA, s01 - lzA));
                __stcs((float2*)&lB[col0],     make_float2(s10 - lzB, s11 - lzB));
                __stcs((float2*)&lA[col0 + 8], make_float2(s20 - lzA, s21 - lzA));
                __stcs((float2*)&lB[col0 + 8], make_float2(s30 - lzB, s31 - lzB));
                __stcs((float2*)&aA[col0],     make_float2(fmaf(t00, izA, izA), fmaf(t01, izA, izA)));
                __stcs((float2*)&aB[col0],     make_float2(fmaf(t10, izB, izB), fmaf(t11, izB, izB)));
                __stcs((float2*)&aA[col0 + 8], make_float2(fmaf(t20, izA, izA), fmaf(t21, izA, izA)));
                __stcs((float2*)&aB[col0 + 8], make_float2(fmaf(t30, izB, izB), fmaf(t31, izB, izB)));
                uint32_t a0 = pack2(t00, t01);
                uint32_t a1 = pack2(t10, t11);
                uint32_t a2 = pack2(t20, t21);
                uint32_t a3 = pack2(t30, t31);
#pragma unroll
                for (int nn2 = 0; nn2 < 4; nn2++) {
                    uint32_t b0, b1, b2, b3;
                    uint32_t addr = smem_u32(&sm0[nt2 * 16 + ((lane >> 3) & 1) * 8 + (lane & 7)]
                                                  [nn2 * 16 + ((lane >> 4) << 3)]);
                    ldmat_x4_t(b0, b1, b2, b3, addr);
                    mma_bf16(acc[2 * nn2][0], acc[2 * nn2][1], acc[2 * nn2][2], acc[2 * nn2][3],
                             a0, a1, a2, a3, b0, b1);
                    mma_bf16(acc[2 * nn2 + 1][0], acc[2 * nn2 + 1][1], acc[2 * nn2 + 1][2], acc[2 * nn2 + 1][3],
                             a0, a1, a2, a3, b2, b3);
                }
            }
        }
    }

    // ---- epilogue: out = (vsum + t@v) / Z ----
    float* oA = out + rowA * 64;
    float* oB = oA + 8 * 64;
#pragma unroll
    for (int nt = 0; nt < 8; nt++) {
        float vs0 = g_vsum[b * 64 + nt * 8 + c2];
        float vs1 = g_vsum[b * 64 + nt * 8 + c2 + 1];
        *(float2*)&oA[nt * 8 + c2] = make_float2((vs0 + acc[nt][0]) * izA,
                                                 (vs1 + acc[nt][1]) * izA);
        *(float2*)&oB[nt * 8 + c2] = make_float2((vs0 + acc[nt][2]) * izB,
                                                 (vs1 + acc[nt][3]) * izB);
    }
}

// ---------------- launcher ----------------
extern "C" void kernel_launch(void* const* d_in, const int* in_sizes, int n_in,
                              void* d_out, int out_size) {
    const float* q = (const float*)d_in[0];
    const float* k = (const float*)d_in[1];
    const float* v = (const float*)d_in[2];

    float* out   = (float*)d_out;                 // [B,L,64]
    float* attn  = out + (long)BL * 64;           // [B,L,L]
    float* lattn = attn + (long)BL * L;           // [B,L,L]

    k_zero<<<128, 256>>>();
    k_prep_qk<<<2 * BL / 8, 256>>>(q, k);
    k_prep_v<<<BL / 64, 256>>>(v);

    dim3 gm(16, B);
    k_moment<<<gm, 256>>>();

    dim3 gz(32, B);
    k_z<<<gz, 256>>>();

    dim3 g(L / 128, B);                           // (16,8) = 128 CTAs
    k_main<<<g, 256>>>(attn, lattn, out);
}